// round 1
// baseline (speedup 1.0000x reference)
#include <cuda_runtime.h>
#include <cstdint>

#define DM 2048
#define DS 16
#define SEQ 4096
#define NB 4
#define NROWS (NB*SEQ)

// ---- scratch (static device arrays: no allocation allowed) ----
__device__ float  g_u[NROWS*DS + 256];   // padded so scan prefetch never needs a bounds check
__device__ float2 g_murs[NROWS];
__device__ float  g_hist[NROWS*DS];
__device__ float  g_cbb[2*DS];           // cB[16], bB[16]

__device__ __forceinline__ float tanh_fast(float x){
    float y;
    asm("tanh.approx.f32 %0, %1;" : "=f"(y) : "f"(x));
    return y;
}

// ---------------------------------------------------------------------------
// kern0: cB[s] = sum_d gamma[d]*B[s][d], bB[s] = sum_d beta[d]*B[s][d]
// ---------------------------------------------------------------------------
__global__ void kern0(const float* __restrict__ B,
                      const float* __restrict__ gamma,
                      const float* __restrict__ beta){
    int s   = blockIdx.x;          // 16 blocks
    int tid = threadIdx.x;         // 256 threads
    float ac = 0.f, ab = 0.f;
    for (int d = tid; d < DM; d += 256){
        float b = B[s*DM + d];
        ac = fmaf(gamma[d], b, ac);
        ab = fmaf(beta[d],  b, ab);
    }
    #pragma unroll
    for (int off = 16; off > 0; off >>= 1){
        ac += __shfl_xor_sync(0xFFFFFFFFu, ac, off);
        ab += __shfl_xor_sync(0xFFFFFFFFu, ab, off);
    }
    __shared__ float sc[8], sb[8];
    int warp = tid >> 5, lane = tid & 31;
    if (lane == 0){ sc[warp] = ac; sb[warp] = ab; }
    __syncthreads();
    if (tid == 0){
        float c = 0.f, b2 = 0.f;
        #pragma unroll
        for (int w = 0; w < 8; w++){ c += sc[w]; b2 += sb[w]; }
        g_cbb[s]      = c;
        g_cbb[DS + s] = b2;
    }
}

// ---------------------------------------------------------------------------
// kernA: per row: LN stats + 16 raw-x dot products against (gamma*B), then
//        u[row][s] = rs*(dot_s - mu*cB[s]) + bB[s].  B cached in registers.
// ---------------------------------------------------------------------------
__global__ __launch_bounds__(256, 1)
void kernA(const float* __restrict__ x,
           const float* __restrict__ B,
           const float* __restrict__ gamma,
           const float* __restrict__ beta){
    const int tid  = threadIdx.x;
    const int lane = tid & 31, warp = tid >> 5;
    const int d0   = tid * 8;

    float gg[8];
    {
        float4 t0 = *(const float4*)(gamma + d0);
        float4 t1 = *(const float4*)(gamma + d0 + 4);
        gg[0]=t0.x; gg[1]=t0.y; gg[2]=t0.z; gg[3]=t0.w;
        gg[4]=t1.x; gg[5]=t1.y; gg[6]=t1.z; gg[7]=t1.w;
    }
    float bg[16][8];                       // gamma-folded B, register-resident
    #pragma unroll
    for (int s = 0; s < 16; s++){
        float4 b0 = *(const float4*)(B + s*DM + d0);
        float4 b1 = *(const float4*)(B + s*DM + d0 + 4);
        bg[s][0]=b0.x*gg[0]; bg[s][1]=b0.y*gg[1]; bg[s][2]=b0.z*gg[2]; bg[s][3]=b0.w*gg[3];
        bg[s][4]=b1.x*gg[4]; bg[s][5]=b1.y*gg[5]; bg[s][6]=b1.z*gg[6]; bg[s][7]=b1.w*gg[7];
    }
    float cB = 0.f, bB = 0.f;
    if (tid < DS){ cB = g_cbb[tid]; bB = g_cbb[DS + tid]; }

    __shared__ float red[8][20];
    __shared__ float bc[20];

    int row = blockIdx.x;
    float4 xa, xb;
    if (row < NROWS){
        xa = *(const float4*)(x + (size_t)row*DM + d0);
        xb = *(const float4*)(x + (size_t)row*DM + d0 + 4);
    }
    for (; row < NROWS; row += gridDim.x){
        float xs[8] = {xa.x, xa.y, xa.z, xa.w, xb.x, xb.y, xb.z, xb.w};
        int nrow = row + gridDim.x;
        if (nrow < NROWS){                  // prefetch next row (hide DRAM latency)
            xa = *(const float4*)(x + (size_t)nrow*DM + d0);
            xb = *(const float4*)(x + (size_t)nrow*DM + d0 + 4);
        }
        float p[18];
        {
            float s1 = 0.f, s2 = 0.f;
            #pragma unroll
            for (int k = 0; k < 8; k++){ s1 += xs[k]; s2 = fmaf(xs[k], xs[k], s2); }
            p[16] = s1; p[17] = s2;
        }
        #pragma unroll
        for (int s = 0; s < 16; s++){
            float acc = xs[0]*bg[s][0];
            #pragma unroll
            for (int k = 1; k < 8; k++) acc = fmaf(xs[k], bg[s][k], acc);
            p[s] = acc;
        }
        // intra-warp butterfly reduce of 18 values
        #pragma unroll
        for (int off = 16; off > 0; off >>= 1){
            #pragma unroll
            for (int i = 0; i < 18; i++)
                p[i] += __shfl_xor_sync(0xFFFFFFFFu, p[i], off);
        }
        if (lane == 0){
            #pragma unroll
            for (int i = 0; i < 18; i++) red[warp][i] = p[i];
        }
        __syncthreads();
        if (tid < 18){
            float t = red[0][tid];
            #pragma unroll
            for (int w = 1; w < 8; w++) t += red[w][tid];
            bc[tid] = t;
        }
        __syncthreads();
        if (tid < 17){
            float mu  = bc[16] * (1.0f/DM);
            float var = bc[17] * (1.0f/DM) - mu*mu;
            float rs  = rsqrtf(var + 1e-5f);
            if (tid < DS){
                g_u[row*DS + tid] = fmaf(-mu, cB, bc[tid]) * rs + bB;
            } else {
                g_murs[row] = make_float2(mu, rs);
            }
        }
        // program-order reads of bc/red precede next iteration's barriers -> safe
    }
}

// ---------------------------------------------------------------------------
// kernB: sequential scan, one warp per batch. Lane s holds h[s] and A column s.
//        h <- tanh(h@A + u_t); history stored for the epilogue.
// ---------------------------------------------------------------------------
__global__ void kernB(const float* __restrict__ A){
    const int b    = blockIdx.x;           // 4 blocks
    const int lane = threadIdx.x;          // 32 threads
    const unsigned FULL = 0xFFFFFFFFu;

    float a[16];
    #pragma unroll
    for (int j = 0; j < 16; j++) a[j] = A[j*DS + (lane & 15)];

    const float* ub = g_u    + b * SEQ * DS;
    float*       hb = g_hist + b * SEQ * DS;

    float h = 0.f;
    float uq[8];
    #pragma unroll
    for (int k = 0; k < 8; k++) uq[k] = ub[k*DS + lane];   // all lanes load (padded array)

    for (int t = 0; t < SEQ; t += 8){
        #pragma unroll
        for (int k = 0; k < 8; k++){
            float uc = uq[k];
            uq[k] = ub[(t + 8 + k)*DS + lane];             // prefetch 8 steps ahead (padded)
            float acc0 = uc, acc1 = 0.f, acc2 = 0.f, acc3 = 0.f;
            #pragma unroll
            for (int j = 0; j < 16; j += 4){
                float s0 = __shfl_sync(FULL, h, j);
                float s1 = __shfl_sync(FULL, h, j+1);
                float s2 = __shfl_sync(FULL, h, j+2);
                float s3 = __shfl_sync(FULL, h, j+3);
                acc0 = fmaf(s0, a[j],   acc0);
                acc1 = fmaf(s1, a[j+1], acc1);
                acc2 = fmaf(s2, a[j+2], acc2);
                acc3 = fmaf(s3, a[j+3], acc3);
            }
            float v = (acc0 + acc1) + (acc2 + acc3);
            h = tanh_fast(v);
            if (lane < DS) hb[(t + k)*DS + lane] = h;
        }
    }
}

// ---------------------------------------------------------------------------
// kernC: out[d] = sum_s h[s]*C[s][d] + (1+Dp[d])*gamma[d]*(x-mu)*rs
//               + (1+Dp[d])*beta[d].   C cached in registers.
// ---------------------------------------------------------------------------
__global__ __launch_bounds__(256, 1)
void kernC(const float* __restrict__ x,
           const float* __restrict__ Cm,
           const float* __restrict__ Dp,
           const float* __restrict__ gamma,
           const float* __restrict__ beta,
           float* __restrict__ out){
    const int tid = threadIdx.x;
    const int d0  = tid * 8;

    float e[8], f[8];
    {
        float4 dp0 = *(const float4*)(Dp    + d0), dp1 = *(const float4*)(Dp    + d0 + 4);
        float4 g0  = *(const float4*)(gamma + d0), g1  = *(const float4*)(gamma + d0 + 4);
        float4 b0  = *(const float4*)(beta  + d0), b1  = *(const float4*)(beta  + d0 + 4);
        float dv[8] = {dp0.x,dp0.y,dp0.z,dp0.w,dp1.x,dp1.y,dp1.z,dp1.w};
        float gv[8] = {g0.x,g0.y,g0.z,g0.w,g1.x,g1.y,g1.z,g1.w};
        float bv[8] = {b0.x,b0.y,b0.z,b0.w,b1.x,b1.y,b1.z,b1.w};
        #pragma unroll
        for (int k = 0; k < 8; k++){
            float c = 1.0f + dv[k];
            e[k] = c * gv[k];
            f[k] = c * bv[k];
        }
    }
    float cr[16][8];
    #pragma unroll
    for (int s = 0; s < 16; s++){
        float4 c0 = *(const float4*)(Cm + s*DM + d0);
        float4 c1 = *(const float4*)(Cm + s*DM + d0 + 4);
        cr[s][0]=c0.x; cr[s][1]=c0.y; cr[s][2]=c0.z; cr[s][3]=c0.w;
        cr[s][4]=c1.x; cr[s][5]=c1.y; cr[s][6]=c1.z; cr[s][7]=c1.w;
    }

    int row = blockIdx.x;
    float4 xa, xb;
    if (row < NROWS){
        xa = *(const float4*)(x + (size_t)row*DM + d0);
        xb = *(const float4*)(x + (size_t)row*DM + d0 + 4);
    }
    for (; row < NROWS; row += gridDim.x){
        float xs[8] = {xa.x, xa.y, xa.z, xa.w, xb.x, xb.y, xb.z, xb.w};
        int nrow = row + gridDim.x;
        if (nrow < NROWS){
            xa = *(const float4*)(x + (size_t)nrow*DM + d0);
            xb = *(const float4*)(x + (size_t)nrow*DM + d0 + 4);
        }
        float2 mr = g_murs[row];
        const float4* hp = (const float4*)(g_hist + row*DS);  // uniform, L2-resident
        float4 h0 = hp[0], h1 = hp[1], h2 = hp[2], h3 = hp[3];
        float hv[16] = {h0.x,h0.y,h0.z,h0.w, h1.x,h1.y,h1.z,h1.w,
                        h2.x,h2.y,h2.z,h2.w, h3.x,h3.y,h3.z,h3.w};
        float o[8];
        #pragma unroll
        for (int k = 0; k < 8; k++){
            float xc  = (xs[k] - mr.x) * mr.y;
            float acc = fmaf(e[k], xc, f[k]);
            #pragma unroll
            for (int s = 0; s < 16; s++) acc = fmaf(hv[s], cr[s][k], acc);
            o[k] = acc;
        }
        *(float4*)(out + (size_t)row*DM + d0)     = make_float4(o[0], o[1], o[2], o[3]);
        *(float4*)(out + (size_t)row*DM + d0 + 4) = make_float4(o[4], o[5], o[6], o[7]);
    }
}

// ---------------------------------------------------------------------------
extern "C" void kernel_launch(void* const* d_in, const int* in_sizes, int n_in,
                              void* d_out, int out_size){
    const float* x     = (const float*)d_in[0];
    const float* A     = (const float*)d_in[1];
    const float* B     = (const float*)d_in[2];
    const float* C     = (const float*)d_in[3];
    const float* Dp    = (const float*)d_in[4];
    const float* gamma = (const float*)d_in[5];
    const float* beta  = (const float*)d_in[6];
    float* out = (float*)d_out;

    kern0<<<DS, 256>>>(B, gamma, beta);
    kernA<<<148, 256>>>(x, B, gamma, beta);
    kernB<<<NB, 32>>>(A);
    kernC<<<148, 256>>>(x, C, Dp, gamma, beta, out);
}

// round 2
// speedup vs baseline: 1.1308x; 1.1308x over previous
#include <cuda_runtime.h>
#include <cstdint>

#define DM 2048
#define DS 16
#define SEQ 4096
#define NB 4
#define NROWS (NB*SEQ)

// ---- scratch (static device arrays: no allocation allowed) ----
__device__ float  g_u[NROWS*DS + 256];   // padded so scan prefetch never needs a bounds check
__device__ float2 g_murs[NROWS];
__device__ float  g_hist[NROWS*DS];
__device__ float  g_cbb[2*DS];           // cB[16], bB[16]

__device__ __forceinline__ float tanh_fast(float x){
    float y;
    asm("tanh.approx.f32 %0, %1;" : "=f"(y) : "f"(x));
    return y;
}

// ---------------------------------------------------------------------------
// kern0: cB[s] = sum_d gamma[d]*B[s][d], bB[s] = sum_d beta[d]*B[s][d]
// ---------------------------------------------------------------------------
__global__ void kern0(const float* __restrict__ B,
                      const float* __restrict__ gamma,
                      const float* __restrict__ beta){
    int s   = blockIdx.x;          // 16 blocks
    int tid = threadIdx.x;         // 256 threads
    float ac = 0.f, ab = 0.f;
    for (int d = tid; d < DM; d += 256){
        float b = B[s*DM + d];
        ac = fmaf(gamma[d], b, ac);
        ab = fmaf(beta[d],  b, ab);
    }
    #pragma unroll
    for (int off = 16; off > 0; off >>= 1){
        ac += __shfl_xor_sync(0xFFFFFFFFu, ac, off);
        ab += __shfl_xor_sync(0xFFFFFFFFu, ab, off);
    }
    __shared__ float sc[8], sb[8];
    int warp = tid >> 5, lane = tid & 31;
    if (lane == 0){ sc[warp] = ac; sb[warp] = ab; }
    __syncthreads();
    if (tid == 0){
        float c = 0.f, b2 = 0.f;
        #pragma unroll
        for (int w = 0; w < 8; w++){ c += sc[w]; b2 += sb[w]; }
        g_cbb[s]      = c;
        g_cbb[DS + s] = b2;
    }
}

// ---------------------------------------------------------------------------
// kernA: per row: LN stats + 16 raw-x dot products against (gamma*B), then
//        u[row][s] = rs*(dot_s - mu*cB[s]) + bB[s].  B cached in registers.
// ---------------------------------------------------------------------------
__global__ __launch_bounds__(256, 1)
void kernA(const float* __restrict__ x,
           const float* __restrict__ B,
           const float* __restrict__ gamma,
           const float* __restrict__ beta){
    const int tid  = threadIdx.x;
    const int lane = tid & 31, warp = tid >> 5;
    const int d0   = tid * 8;

    float gg[8];
    {
        float4 t0 = *(const float4*)(gamma + d0);
        float4 t1 = *(const float4*)(gamma + d0 + 4);
        gg[0]=t0.x; gg[1]=t0.y; gg[2]=t0.z; gg[3]=t0.w;
        gg[4]=t1.x; gg[5]=t1.y; gg[6]=t1.z; gg[7]=t1.w;
    }
    float bg[16][8];                       // gamma-folded B, register-resident
    #pragma unroll
    for (int s = 0; s < 16; s++){
        float4 b0 = *(const float4*)(B + s*DM + d0);
        float4 b1 = *(const float4*)(B + s*DM + d0 + 4);
        bg[s][0]=b0.x*gg[0]; bg[s][1]=b0.y*gg[1]; bg[s][2]=b0.z*gg[2]; bg[s][3]=b0.w*gg[3];
        bg[s][4]=b1.x*gg[4]; bg[s][5]=b1.y*gg[5]; bg[s][6]=b1.z*gg[6]; bg[s][7]=b1.w*gg[7];
    }
    float cB = 0.f, bB = 0.f;
    if (tid < DS){ cB = g_cbb[tid]; bB = g_cbb[DS + tid]; }

    __shared__ float red[8][20];
    __shared__ float bc[20];

    int row = blockIdx.x;
    float4 xa, xb;
    if (row < NROWS){
        xa = *(const float4*)(x + (size_t)row*DM + d0);
        xb = *(const float4*)(x + (size_t)row*DM + d0 + 4);
    }
    for (; row < NROWS; row += gridDim.x){
        float xs[8] = {xa.x, xa.y, xa.z, xa.w, xb.x, xb.y, xb.z, xb.w};
        int nrow = row + gridDim.x;
        if (nrow < NROWS){                  // prefetch next row (hide DRAM latency)
            xa = *(const float4*)(x + (size_t)nrow*DM + d0);
            xb = *(const float4*)(x + (size_t)nrow*DM + d0 + 4);
        }
        float p[18];
        {
            float s1 = 0.f, s2 = 0.f;
            #pragma unroll
            for (int k = 0; k < 8; k++){ s1 += xs[k]; s2 = fmaf(xs[k], xs[k], s2); }
            p[16] = s1; p[17] = s2;
        }
        #pragma unroll
        for (int s = 0; s < 16; s++){
            float acc = xs[0]*bg[s][0];
            #pragma unroll
            for (int k = 1; k < 8; k++) acc = fmaf(xs[k], bg[s][k], acc);
            p[s] = acc;
        }
        // intra-warp butterfly reduce of 18 values
        #pragma unroll
        for (int off = 16; off > 0; off >>= 1){
            #pragma unroll
            for (int i = 0; i < 18; i++)
                p[i] += __shfl_xor_sync(0xFFFFFFFFu, p[i], off);
        }
        if (lane == 0){
            #pragma unroll
            for (int i = 0; i < 18; i++) red[warp][i] = p[i];
        }
        __syncthreads();
        if (tid < 18){
            float t = red[0][tid];
            #pragma unroll
            for (int w = 1; w < 8; w++) t += red[w][tid];
            bc[tid] = t;
        }
        __syncthreads();
        if (tid < 17){
            float mu  = bc[16] * (1.0f/DM);
            float var = bc[17] * (1.0f/DM) - mu*mu;
            float rs  = rsqrtf(var + 1e-5f);
            if (tid < DS){
                g_u[row*DS + tid] = fmaf(-mu, cB, bc[tid]) * rs + bB;
            } else {
                g_murs[row] = make_float2(mu, rs);
            }
        }
        // program-order reads of bc/red precede next iteration's barriers -> safe
    }
}

// ---------------------------------------------------------------------------
// kernB: sequential scan, one warp per batch (one block = one warp).
//        State broadcast via double-buffered SMEM + single-warp BAR.SYNC
//        (3-cycle floor) instead of 16 SHFLs (MIO-issue-bound).
// ---------------------------------------------------------------------------
__global__ __launch_bounds__(32, 1)
void kernB(const float* __restrict__ A){
    __shared__ float sh[2][32];
    const int b    = blockIdx.x;           // 4 blocks
    const int lane = threadIdx.x;          // 32 threads (lanes 16-31 redundant)

    float a[16];
    #pragma unroll
    for (int j = 0; j < 16; j++) a[j] = A[j*DS + (lane & 15)];

    const float* ub = g_u    + b * SEQ * DS;
    float*       hb = g_hist + b * SEQ * DS;

    sh[0][lane] = 0.f;                     // h_0 = 0 lives in buffer 0
    __syncthreads();

    float uq[8];
    #pragma unroll
    for (int k = 0; k < 8; k++) uq[k] = ub[k*DS + lane];   // padded array: all lanes safe

    for (int t = 0; t < SEQ; t += 8){
        #pragma unroll
        for (int k = 0; k < 8; k++){
            const int p = k & 1;           // buffer holding current state
            float uc = uq[k];
            uq[k] = ub[(t + 8 + k)*DS + lane];             // prefetch 8 steps ahead (padded)

            float4 H0 = *(const float4*)&sh[p][0];
            float4 H1 = *(const float4*)&sh[p][4];
            float4 H2 = *(const float4*)&sh[p][8];
            float4 H3 = *(const float4*)&sh[p][12];

            float acc0 = fmaf(H0.x, a[0],  uc);
            float acc1 = H0.y * a[1];
            float acc2 = H0.z * a[2];
            float acc3 = H0.w * a[3];
            acc0 = fmaf(H1.x, a[4],  acc0);
            acc1 = fmaf(H1.y, a[5],  acc1);
            acc2 = fmaf(H1.z, a[6],  acc2);
            acc3 = fmaf(H1.w, a[7],  acc3);
            acc0 = fmaf(H2.x, a[8],  acc0);
            acc1 = fmaf(H2.y, a[9],  acc1);
            acc2 = fmaf(H2.z, a[10], acc2);
            acc3 = fmaf(H2.w, a[11], acc3);
            acc0 = fmaf(H3.x, a[12], acc0);
            acc1 = fmaf(H3.y, a[13], acc1);
            acc2 = fmaf(H3.z, a[14], acc2);
            acc3 = fmaf(H3.w, a[15], acc3);
            float v = (acc0 + acc1) + (acc2 + acc3);
            float h = tanh_fast(v);

            sh[p ^ 1][lane] = h;           // publish next state to other buffer
            __syncthreads();               // 1 warp -> BAR floor ~3cy, drains STS

            if (lane < DS) hb[(t + k)*DS + lane] = h;
        }
    }
}

// ---------------------------------------------------------------------------
// kernC: out[d] = sum_s h[s]*C[s][d] + (1+Dp[d])*gamma[d]*(x-mu)*rs
//               + (1+Dp[d])*beta[d].
//        DM split across 2 blocks -> C tile = 64 regs -> 2 blocks/SM.
// ---------------------------------------------------------------------------
__global__ __launch_bounds__(256, 2)
void kernC(const float* __restrict__ x,
           const float* __restrict__ Cm,
           const float* __restrict__ Dp,
           const float* __restrict__ gamma,
           const float* __restrict__ beta,
           float* __restrict__ out){
    const int tid  = threadIdx.x;
    const int half = blockIdx.x & 1;
    const int d0   = half * (DM/2) + tid * 4;

    float e[4], f[4];
    {
        float4 dp = *(const float4*)(Dp    + d0);
        float4 g  = *(const float4*)(gamma + d0);
        float4 bt = *(const float4*)(beta  + d0);
        float dv[4] = {dp.x,dp.y,dp.z,dp.w};
        float gv[4] = {g.x,g.y,g.z,g.w};
        float bv[4] = {bt.x,bt.y,bt.z,bt.w};
        #pragma unroll
        for (int k = 0; k < 4; k++){
            float c = 1.0f + dv[k];
            e[k] = c * gv[k];
            f[k] = c * bv[k];
        }
    }
    float cr[16][4];
    #pragma unroll
    for (int s = 0; s < 16; s++){
        float4 c0 = *(const float4*)(Cm + s*DM + d0);
        cr[s][0]=c0.x; cr[s][1]=c0.y; cr[s][2]=c0.z; cr[s][3]=c0.w;
    }

    int row = blockIdx.x >> 1;
    float4 xa;
    if (row < NROWS){
        xa = *(const float4*)(x + (size_t)row*DM + d0);
    }
    for (; row < NROWS; row += 148){
        float xs[4] = {xa.x, xa.y, xa.z, xa.w};
        int nrow = row + 148;
        if (nrow < NROWS){
            xa = *(const float4*)(x + (size_t)nrow*DM + d0);
        }
        float2 mr = g_murs[row];
        const float4* hp = (const float4*)(g_hist + row*DS);  // uniform, L2-resident
        float4 h0 = hp[0], h1 = hp[1], h2 = hp[2], h3 = hp[3];
        float hv[16] = {h0.x,h0.y,h0.z,h0.w, h1.x,h1.y,h1.z,h1.w,
                        h2.x,h2.y,h2.z,h2.w, h3.x,h3.y,h3.z,h3.w};
        float o[4];
        #pragma unroll
        for (int k = 0; k < 4; k++){
            float xc  = (xs[k] - mr.x) * mr.y;
            float acc = fmaf(e[k], xc, f[k]);
            #pragma unroll
            for (int s = 0; s < 16; s++) acc = fmaf(hv[s], cr[s][k], acc);
            o[k] = acc;
        }
        *(float4*)(out + (size_t)row*DM + d0) = make_float4(o[0], o[1], o[2], o[3]);
    }
}

// ---------------------------------------------------------------------------
extern "C" void kernel_launch(void* const* d_in, const int* in_sizes, int n_in,
                              void* d_out, int out_size){
    const float* x     = (const float*)d_in[0];
    const float* A     = (const float*)d_in[1];
    const float* B     = (const float*)d_in[2];
    const float* C     = (const float*)d_in[3];
    const float* Dp    = (const float*)d_in[4];
    const float* gamma = (const float*)d_in[5];
    const float* beta  = (const float*)d_in[6];
    float* out = (float*)d_out;

    kern0<<<DS, 256>>>(B, gamma, beta);
    kernA<<<148, 256>>>(x, B, gamma, beta);
    kernB<<<NB, 32>>>(A);
    kernC<<<296, 256>>>(x, C, Dp, gamma, beta, out);
}